// round 1
// baseline (speedup 1.0000x reference)
#include <cuda_runtime.h>
#include <cstdint>

#define NN   100000
#define INC  256
#define OUTC 256
#define EE   500000
#define KK   1024   // 4 * 256 concatenated aggregation channels

// ------------------------- device scratch (static: no allocs allowed) ------
__device__ float g_agg[(size_t)NN * KK];     // [N][4*256] aggregated features
__device__ float g_Bm[KK * OUTC];            // stacked W_k * diag(p_{k+2})
__device__ float g_cb[OUTC];                 // sum_k b_k * p_{k+2}
__device__ int   g_cnt[4][NN];
__device__ int   g_cur[4][NN];
__device__ int   g_rs[4][NN + 1];
__device__ float g_dis[4][NN];
__device__ int   g_srcv[4][EE];

// ------------------------- prep kernels ------------------------------------
__global__ void k_init() {
    int i = blockIdx.x * blockDim.x + threadIdx.x;
    if (i < 4 * NN) ((int*)g_cnt)[i] = 0;
}

__global__ void k_hist(const int* __restrict__ e0, const int* __restrict__ e1,
                       const int* __restrict__ e2, const int* __restrict__ e3) {
    int e = blockIdx.x * blockDim.x + threadIdx.x;
    if (e >= EE) return;
    int k = blockIdx.y;
    const int* ep = (k == 0) ? e0 : (k == 1) ? e1 : (k == 2) ? e2 : e3;
    int col = ep[EE + e];
    atomicAdd(&g_cnt[k][col], 1);
}

// one CTA per graph: exclusive scan of counts -> row_start, plus dis=rsqrt(deg)
__global__ void k_scan() {
    int k = blockIdx.x;
    int tid = threadIdx.x;
    const int CH = (NN + 1023) / 1024;
    int start = tid * CH;
    int end = min(start + CH, NN);
    int s = 0;
    for (int i = start; i < end; i++) s += g_cnt[k][i];
    __shared__ int sm[1024];
    sm[tid] = s;
    __syncthreads();
    for (int d = 1; d < 1024; d <<= 1) {
        int v = 0;
        if (tid >= d) v = sm[tid - d];
        __syncthreads();
        sm[tid] += v;
        __syncthreads();
    }
    int run = tid ? sm[tid - 1] : 0;
    for (int i = start; i < end; i++) {
        int c = g_cnt[k][i];
        g_rs[k][i] = run;
        run += c;
        g_dis[k][i] = rsqrtf((float)(c + 1));  // deg includes self-loop
        g_cur[k][i] = 0;
    }
    if (tid == 0) g_rs[k][NN] = sm[1023];
}

__global__ void k_fill(const int* __restrict__ e0, const int* __restrict__ e1,
                       const int* __restrict__ e2, const int* __restrict__ e3) {
    int e = blockIdx.x * blockDim.x + threadIdx.x;
    if (e >= EE) return;
    int k = blockIdx.y;
    const int* ep = (k == 0) ? e0 : (k == 1) ? e1 : (k == 2) ? e2 : e3;
    int row = ep[e];
    int col = ep[EE + e];
    int ofs = atomicAdd(&g_cur[k][col], 1);
    g_srcv[k][g_rs[k][col] + ofs] = row;
}

__global__ void k_bmat(const float* __restrict__ W1, const float* __restrict__ W2,
                       const float* __restrict__ W3, const float* __restrict__ W4,
                       const float* __restrict__ p2, const float* __restrict__ p3,
                       const float* __restrict__ p4, const float* __restrict__ p5) {
    int r = blockIdx.x;       // 0..1023 : k = r>>8, c = r&255
    int j = threadIdx.x;      // 0..255
    int k = r >> 8, c = r & 255;
    const float* W = (k == 0) ? W1 : (k == 1) ? W2 : (k == 2) ? W3 : W4;
    const float* p = (k == 0) ? p2 : (k == 1) ? p3 : (k == 2) ? p4 : p5;
    g_Bm[r * OUTC + j] = W[c * OUTC + j] * p[j];
}

__global__ void k_cbias(const float* __restrict__ b1, const float* __restrict__ b2,
                        const float* __restrict__ b3, const float* __restrict__ b4,
                        const float* __restrict__ p2, const float* __restrict__ p3,
                        const float* __restrict__ p4, const float* __restrict__ p5) {
    int j = threadIdx.x;
    g_cb[j] = b1[j] * p2[j] + b2[j] * p3[j] + b3[j] * p4[j] + b4[j] * p5[j];
}

// ------------------------- aggregation: AGG[n][k*256+c] = (Â_k x)[n][c] ----
// one warp per (node, graph) pair; lane owns 8 channels (2 float4)
__global__ void k_agg(const float* __restrict__ x) {
    int wid = threadIdx.x >> 5;
    int lane = threadIdx.x & 31;
    int pair = blockIdx.x * 8 + wid;       // 4e5 pairs
    int n = pair >> 2;
    int k = pair & 3;

    float dn = g_dis[k][n];
    int rs0 = g_rs[k][n];
    int rs1 = g_rs[k][n + 1];

    const float4* xr = (const float4*)(x + (size_t)n * INC);
    float sw = dn * dn;                    // self-loop norm = 1/deg
    float4 v0 = xr[lane * 2];
    float4 v1 = xr[lane * 2 + 1];
    float4 a0 = make_float4(sw * v0.x, sw * v0.y, sw * v0.z, sw * v0.w);
    float4 a1 = make_float4(sw * v1.x, sw * v1.y, sw * v1.z, sw * v1.w);

    for (int p = rs0; p < rs1; ++p) {
        int src = g_srcv[k][p];
        float w = g_dis[k][src] * dn;
        const float4* xs = (const float4*)(x + (size_t)src * INC);
        float4 u0 = xs[lane * 2];
        float4 u1 = xs[lane * 2 + 1];
        a0.x += w * u0.x; a0.y += w * u0.y; a0.z += w * u0.z; a0.w += w * u0.w;
        a1.x += w * u1.x; a1.y += w * u1.y; a1.z += w * u1.z; a1.w += w * u1.w;
    }

    float4* op = (float4*)(g_agg + (size_t)n * KK + k * OUTC);
    op[lane * 2] = a0;
    op[lane * 2 + 1] = a1;
}

// ------------------------- tf32 GEMM + fused epilogue -----------------------
// out[N,256] = AGG[N,1024] @ g_Bm[1024,256] + x0c*p0 + x1c*p1 + cb
__device__ __forceinline__ uint32_t f2tf(float f) {
    uint32_t r;
    asm("cvt.rna.tf32.f32 %0, %1;" : "=r"(r) : "f"(f));
    return r;
}

__device__ __forceinline__ void mma8(float* d, const uint32_t* a, const uint32_t* b) {
    asm volatile(
        "mma.sync.aligned.m16n8k8.row.col.f32.tf32.tf32.f32 "
        "{%0,%1,%2,%3}, {%4,%5,%6,%7}, {%8,%9}, {%0,%1,%2,%3};\n"
        : "+f"(d[0]), "+f"(d[1]), "+f"(d[2]), "+f"(d[3])
        : "r"(a[0]), "r"(a[1]), "r"(a[2]), "r"(a[3]), "r"(b[0]), "r"(b[1]));
}

#define BM 128
#define BN 128
#define BKC 16
#define NCHUNK (KK / BKC)   // 64

__global__ __launch_bounds__(256, 2) void k_gemm(
    const float* __restrict__ x,
    const float* __restrict__ t0, const float* __restrict__ t1,
    const float* __restrict__ p0, const float* __restrict__ p1,
    float* __restrict__ out) {
    __shared__ float As[2][BM][20];    // pad 16->20: conflict-free frag loads
    __shared__ float Bs[2][BKC][136];  // pad 128->136

    int tid = threadIdx.x;
    int lane = tid & 31;
    int wid = tid >> 5;
    int wm = wid >> 1;   // 0..3  (rows wm*32)
    int wn = wid & 1;    // 0..1  (cols wn*64)
    int bm0 = blockIdx.y * BM;
    int bn0 = blockIdx.x * BN;

    float acc[2][8][4];
#pragma unroll
    for (int mi = 0; mi < 2; mi++)
#pragma unroll
        for (int ni = 0; ni < 8; ni++)
#pragma unroll
            for (int q = 0; q < 4; q++) acc[mi][ni][q] = 0.f;

    float4 ra[2], rb[2];

    auto gld = [&](int c) {
        int k0 = c * BKC;
#pragma unroll
        for (int s = 0; s < 2; s++) {
            int row = (tid >> 2) + s * 64;
            int col = (tid & 3) * 4;
            int gr = bm0 + row;
            if (gr < NN)
                ra[s] = *(const float4*)(g_agg + (size_t)gr * KK + k0 + col);
            else
                ra[s] = make_float4(0.f, 0.f, 0.f, 0.f);
        }
#pragma unroll
        for (int s = 0; s < 2; s++) {
            int row = (tid >> 5) + s * 8;
            int col = (tid & 31) * 4;
            rb[s] = *(const float4*)(g_Bm + (size_t)(k0 + row) * OUTC + bn0 + col);
        }
    };

    auto sts = [&](int buf) {
#pragma unroll
        for (int s = 0; s < 2; s++) {
            int row = (tid >> 2) + s * 64;
            int col = (tid & 3) * 4;
            float* d = &As[buf][row][col];
            d[0] = __uint_as_float(f2tf(ra[s].x));
            d[1] = __uint_as_float(f2tf(ra[s].y));
            d[2] = __uint_as_float(f2tf(ra[s].z));
            d[3] = __uint_as_float(f2tf(ra[s].w));
        }
#pragma unroll
        for (int s = 0; s < 2; s++) {
            int row = (tid >> 5) + s * 8;
            int col = (tid & 31) * 4;
            float* d = &Bs[buf][row][col];
            d[0] = __uint_as_float(f2tf(rb[s].x));
            d[1] = __uint_as_float(f2tf(rb[s].y));
            d[2] = __uint_as_float(f2tf(rb[s].z));
            d[3] = __uint_as_float(f2tf(rb[s].w));
        }
    };

    int g = lane >> 2, t = lane & 3;

    auto compute = [&](int buf) {
#pragma unroll
        for (int ks = 0; ks < 2; ks++) {
            uint32_t af[2][4], bf[8][2];
#pragma unroll
            for (int mi = 0; mi < 2; mi++) {
                int r = wm * 32 + mi * 16 + g;
                int cc = ks * 8 + t;
                af[mi][0] = __float_as_uint(As[buf][r][cc]);
                af[mi][1] = __float_as_uint(As[buf][r + 8][cc]);
                af[mi][2] = __float_as_uint(As[buf][r][cc + 4]);
                af[mi][3] = __float_as_uint(As[buf][r + 8][cc + 4]);
            }
#pragma unroll
            for (int ni = 0; ni < 8; ni++) {
                int br = ks * 8 + t;
                int bc = wn * 64 + ni * 8 + g;
                bf[ni][0] = __float_as_uint(Bs[buf][br][bc]);
                bf[ni][1] = __float_as_uint(Bs[buf][br + 4][bc]);
            }
#pragma unroll
            for (int mi = 0; mi < 2; mi++)
#pragma unroll
                for (int ni = 0; ni < 8; ni++) mma8(acc[mi][ni], af[mi], bf[ni]);
        }
    };

    gld(0);
    sts(0);
    __syncthreads();
    int buf = 0;
    for (int c = 0; c < NCHUNK; c++) {
        if (c + 1 < NCHUNK) gld(c + 1);
        compute(buf);
        __syncthreads();
        if (c + 1 < NCHUNK) {
            sts(buf ^ 1);
            buf ^= 1;
            __syncthreads();
        }
    }

    // epilogue: + x0c*p0 + x1c*p1 + cb, store fp32
#pragma unroll
    for (int mi = 0; mi < 2; mi++) {
#pragma unroll
        for (int rsel = 0; rsel < 2; rsel++) {
            int r = bm0 + wm * 32 + mi * 16 + g + rsel * 8;
            if (r >= NN) continue;
            float xv = x[(size_t)r * INC];
            float x0c = t0[r] * xv;
            float x1c = t1[r] * xv;
#pragma unroll
            for (int ni = 0; ni < 8; ni++) {
                int col = bn0 + wn * 64 + ni * 8 + t * 2;
                float v0 = acc[mi][ni][rsel * 2 + 0] + x0c * __ldg(&p0[col]) +
                           x1c * __ldg(&p1[col]) + g_cb[col];
                float v1 = acc[mi][ni][rsel * 2 + 1] + x0c * __ldg(&p0[col + 1]) +
                           x1c * __ldg(&p1[col + 1]) + g_cb[col + 1];
                *(float2*)(out + (size_t)r * OUTC + col) = make_float2(v0, v1);
            }
        }
    }
}

// ------------------------- launch ------------------------------------------
extern "C" void kernel_launch(void* const* d_in, const int* in_sizes, int n_in,
                              void* d_out, int out_size) {
    const float* x  = (const float*)d_in[0];
    const int* e00  = (const int*)d_in[1];
    const int* e01  = (const int*)d_in[2];
    const int* e10  = (const int*)d_in[3];
    const int* e11  = (const int*)d_in[4];
    const float* t0 = (const float*)d_in[5];
    const float* t1 = (const float*)d_in[6];
    const float* W1 = (const float*)d_in[7];
    const float* b1 = (const float*)d_in[8];
    const float* W2 = (const float*)d_in[9];
    const float* b2 = (const float*)d_in[10];
    const float* W3 = (const float*)d_in[11];
    const float* b3 = (const float*)d_in[12];
    const float* W4 = (const float*)d_in[13];
    const float* b4 = (const float*)d_in[14];
    const float* p0 = (const float*)d_in[15];
    const float* p1 = (const float*)d_in[16];
    const float* p2 = (const float*)d_in[17];
    const float* p3 = (const float*)d_in[18];
    const float* p4 = (const float*)d_in[19];
    const float* p5 = (const float*)d_in[20];
    float* out = (float*)d_out;

    k_init<<<(4 * NN + 255) / 256, 256>>>();
    dim3 ge((EE + 255) / 256, 4);
    k_hist<<<ge, 256>>>(e00, e01, e10, e11);
    k_scan<<<4, 1024>>>();
    k_fill<<<ge, 256>>>(e00, e01, e10, e11);
    k_bmat<<<1024, 256>>>(W1, W2, W3, W4, p2, p3, p4, p5);
    k_cbias<<<1, 256>>>(b1, b2, b3, b4, p2, p3, p4, p5);
    k_agg<<<(4 * NN) / 8, 256>>>(x);
    dim3 gg(OUTC / BN, (NN + BM - 1) / BM);  // (2, 782)
    k_gemm<<<gg, 256>>>(x, t0, t1, p0, p1, out);
}

// round 2
// speedup vs baseline: 1.0007x; 1.0007x over previous
#include <cuda_runtime.h>
#include <cstdint>

#define NN   100000
#define INC  256
#define OUTC 256
#define EE   500000
#define KK   1024   // 4 * 256 concatenated aggregation channels

// ------------------------- device scratch (static: no allocs allowed) ------
__device__ float g_agg[(size_t)NN * KK];     // [N][4*256] aggregated features
__device__ float g_Bm[KK * OUTC];            // stacked W_k * diag(p_{k+2})
__device__ float g_cb[OUTC];                 // sum_k b_k * p_{k+2}
__device__ int   g_cnt[4][NN];
__device__ int   g_cur[4][NN];
__device__ int   g_rs[4][NN + 1];
__device__ float g_dis[4][NN];
__device__ int   g_srcv[4][EE];

// ------------------------- prep kernels ------------------------------------
__global__ void k_init() {
    int i = blockIdx.x * blockDim.x + threadIdx.x;
    if (i < 4 * NN) ((int*)g_cnt)[i] = 0;
}

__global__ void k_hist(const int* __restrict__ e0, const int* __restrict__ e1,
                       const int* __restrict__ e2, const int* __restrict__ e3) {
    int e = blockIdx.x * blockDim.x + threadIdx.x;
    if (e >= EE) return;
    int k = blockIdx.y;
    const int* ep = (k == 0) ? e0 : (k == 1) ? e1 : (k == 2) ? e2 : e3;
    int col = ep[EE + e];
    atomicAdd(&g_cnt[k][col], 1);
}

// one CTA per graph: exclusive scan of counts -> row_start, plus dis=rsqrt(deg)
__global__ void k_scan() {
    int k = blockIdx.x;
    int tid = threadIdx.x;
    const int CH = (NN + 1023) / 1024;
    int start = tid * CH;
    int end = min(start + CH, NN);
    int s = 0;
    for (int i = start; i < end; i++) s += g_cnt[k][i];
    __shared__ int sm[1024];
    sm[tid] = s;
    __syncthreads();
    for (int d = 1; d < 1024; d <<= 1) {
        int v = 0;
        if (tid >= d) v = sm[tid - d];
        __syncthreads();
        sm[tid] += v;
        __syncthreads();
    }
    int run = tid ? sm[tid - 1] : 0;
    for (int i = start; i < end; i++) {
        int c = g_cnt[k][i];
        g_rs[k][i] = run;
        run += c;
        g_dis[k][i] = rsqrtf((float)(c + 1));  // deg includes self-loop
        g_cur[k][i] = 0;
    }
    if (tid == 0) g_rs[k][NN] = sm[1023];
}

__global__ void k_fill(const int* __restrict__ e0, const int* __restrict__ e1,
                       const int* __restrict__ e2, const int* __restrict__ e3) {
    int e = blockIdx.x * blockDim.x + threadIdx.x;
    if (e >= EE) return;
    int k = blockIdx.y;
    const int* ep = (k == 0) ? e0 : (k == 1) ? e1 : (k == 2) ? e2 : e3;
    int row = ep[e];
    int col = ep[EE + e];
    int ofs = atomicAdd(&g_cur[k][col], 1);
    g_srcv[k][g_rs[k][col] + ofs] = row;
}

__global__ void k_bmat(const float* __restrict__ W1, const float* __restrict__ W2,
                       const float* __restrict__ W3, const float* __restrict__ W4,
                       const float* __restrict__ p2, const float* __restrict__ p3,
                       const float* __restrict__ p4, const float* __restrict__ p5) {
    int r = blockIdx.x;       // 0..1023 : k = r>>8, c = r&255
    int j = threadIdx.x;      // 0..255
    int k = r >> 8, c = r & 255;
    const float* W = (k == 0) ? W1 : (k == 1) ? W2 : (k == 2) ? W3 : W4;
    const float* p = (k == 0) ? p2 : (k == 1) ? p3 : (k == 2) ? p4 : p5;
    g_Bm[r * OUTC + j] = W[c * OUTC + j] * p[j];
}

__global__ void k_cbias(const float* __restrict__ b1, const float* __restrict__ b2,
                        const float* __restrict__ b3, const float* __restrict__ b4,
                        const float* __restrict__ p2, const float* __restrict__ p3,
                        const float* __restrict__ p4, const float* __restrict__ p5) {
    int j = threadIdx.x;
    g_cb[j] = b1[j] * p2[j] + b2[j] * p3[j] + b3[j] * p4[j] + b4[j] * p5[j];
}

// ------------------------- aggregation: AGG[n][k*256+c] = (Â_k x)[n][c] ----
// one warp per (node, graph) pair; lane owns 8 channels (2 float4)
__global__ void k_agg(const float* __restrict__ x) {
    int wid = threadIdx.x >> 5;
    int lane = threadIdx.x & 31;
    int pair = blockIdx.x * 8 + wid;       // 4e5 pairs
    int n = pair >> 2;
    int k = pair & 3;

    float dn = g_dis[k][n];
    int rs0 = g_rs[k][n];
    int rs1 = g_rs[k][n + 1];

    const float4* xr = (const float4*)(x + (size_t)n * INC);
    float sw = dn * dn;                    // self-loop norm = 1/deg
    float4 v0 = xr[lane * 2];
    float4 v1 = xr[lane * 2 + 1];
    float4 a0 = make_float4(sw * v0.x, sw * v0.y, sw * v0.z, sw * v0.w);
    float4 a1 = make_float4(sw * v1.x, sw * v1.y, sw * v1.z, sw * v1.w);

    for (int p = rs0; p < rs1; ++p) {
        int src = g_srcv[k][p];
        float w = g_dis[k][src] * dn;
        const float4* xs = (const float4*)(x + (size_t)src * INC);
        float4 u0 = xs[lane * 2];
        float4 u1 = xs[lane * 2 + 1];
        a0.x += w * u0.x; a0.y += w * u0.y; a0.z += w * u0.z; a0.w += w * u0.w;
        a1.x += w * u1.x; a1.y += w * u1.y; a1.z += w * u1.z; a1.w += w * u1.w;
    }

    float4* op = (float4*)(g_agg + (size_t)n * KK + k * OUTC);
    op[lane * 2] = a0;
    op[lane * 2 + 1] = a1;
}

// ------------------------- tf32 GEMM + fused epilogue -----------------------
// out[N,256] = AGG[N,1024] @ g_Bm[1024,256] + x0c*p0 + x1c*p1 + cb
__device__ __forceinline__ uint32_t f2tf(float f) {
    uint32_t r;
    asm("cvt.rna.tf32.f32 %0, %1;" : "=r"(r) : "f"(f));
    return r;
}

__device__ __forceinline__ void mma8(float* d, const uint32_t* a, const uint32_t* b) {
    asm volatile(
        "mma.sync.aligned.m16n8k8.row.col.f32.tf32.tf32.f32 "
        "{%0,%1,%2,%3}, {%4,%5,%6,%7}, {%8,%9}, {%0,%1,%2,%3};\n"
        : "+f"(d[0]), "+f"(d[1]), "+f"(d[2]), "+f"(d[3])
        : "r"(a[0]), "r"(a[1]), "r"(a[2]), "r"(a[3]), "r"(b[0]), "r"(b[1]));
}

#define BM 128
#define BN 128
#define BKC 16
#define NCHUNK (KK / BKC)   // 64

__global__ __launch_bounds__(256, 2) void k_gemm(
    const float* __restrict__ x,
    const float* __restrict__ t0, const float* __restrict__ t1,
    const float* __restrict__ p0, const float* __restrict__ p1,
    float* __restrict__ out) {
    __shared__ float As[2][BM][20];    // pad 16->20: conflict-free frag loads
    __shared__ float Bs[2][BKC][136];  // pad 128->136

    int tid = threadIdx.x;
    int lane = tid & 31;
    int wid = tid >> 5;
    int wm = wid >> 1;   // 0..3  (rows wm*32)
    int wn = wid & 1;    // 0..1  (cols wn*64)
    int bm0 = blockIdx.y * BM;
    int bn0 = blockIdx.x * BN;

    float acc[2][8][4];
#pragma unroll
    for (int mi = 0; mi < 2; mi++)
#pragma unroll
        for (int ni = 0; ni < 8; ni++)
#pragma unroll
            for (int q = 0; q < 4; q++) acc[mi][ni][q] = 0.f;

    float4 ra[2], rb[2];

    auto gld = [&](int c) {
        int k0 = c * BKC;
#pragma unroll
        for (int s = 0; s < 2; s++) {
            int row = (tid >> 2) + s * 64;
            int col = (tid & 3) * 4;
            int gr = bm0 + row;
            if (gr < NN)
                ra[s] = *(const float4*)(g_agg + (size_t)gr * KK + k0 + col);
            else
                ra[s] = make_float4(0.f, 0.f, 0.f, 0.f);
        }
#pragma unroll
        for (int s = 0; s < 2; s++) {
            int row = (tid >> 5) + s * 8;
            int col = (tid & 31) * 4;
            rb[s] = *(const float4*)(g_Bm + (size_t)(k0 + row) * OUTC + bn0 + col);
        }
    };

    auto sts = [&](int buf) {
#pragma unroll
        for (int s = 0; s < 2; s++) {
            int row = (tid >> 2) + s * 64;
            int col = (tid & 3) * 4;
            float* d = &As[buf][row][col];
            d[0] = __uint_as_float(f2tf(ra[s].x));
            d[1] = __uint_as_float(f2tf(ra[s].y));
            d[2] = __uint_as_float(f2tf(ra[s].z));
            d[3] = __uint_as_float(f2tf(ra[s].w));
        }
#pragma unroll
        for (int s = 0; s < 2; s++) {
            int row = (tid >> 5) + s * 8;
            int col = (tid & 31) * 4;
            float* d = &Bs[buf][row][col];
            d[0] = __uint_as_float(f2tf(rb[s].x));
            d[1] = __uint_as_float(f2tf(rb[s].y));
            d[2] = __uint_as_float(f2tf(rb[s].z));
            d[3] = __uint_as_float(f2tf(rb[s].w));
        }
    };

    int g = lane >> 2, t = lane & 3;

    auto compute = [&](int buf) {
#pragma unroll
        for (int ks = 0; ks < 2; ks++) {
            uint32_t af[2][4], bf[8][2];
#pragma unroll
            for (int mi = 0; mi < 2; mi++) {
                int r = wm * 32 + mi * 16 + g;
                int cc = ks * 8 + t;
                af[mi][0] = __float_as_uint(As[buf][r][cc]);
                af[mi][1] = __float_as_uint(As[buf][r + 8][cc]);
                af[mi][2] = __float_as_uint(As[buf][r][cc + 4]);
                af[mi][3] = __float_as_uint(As[buf][r + 8][cc + 4]);
            }
#pragma unroll
            for (int ni = 0; ni < 8; ni++) {
                int br = ks * 8 + t;
                int bc = wn * 64 + ni * 8 + g;
                bf[ni][0] = __float_as_uint(Bs[buf][br][bc]);
                bf[ni][1] = __float_as_uint(Bs[buf][br + 4][bc]);
            }
#pragma unroll
            for (int mi = 0; mi < 2; mi++)
#pragma unroll
                for (int ni = 0; ni < 8; ni++) mma8(acc[mi][ni], af[mi], bf[ni]);
        }
    };

    gld(0);
    sts(0);
    __syncthreads();
    int buf = 0;
    for (int c = 0; c < NCHUNK; c++) {
        if (c + 1 < NCHUNK) gld(c + 1);
        compute(buf);
        __syncthreads();
        if (c + 1 < NCHUNK) {
            sts(buf ^ 1);
            buf ^= 1;
            __syncthreads();
        }
    }

    // epilogue: + x0c*p0 + x1c*p1 + cb, store fp32
#pragma unroll
    for (int mi = 0; mi < 2; mi++) {
#pragma unroll
        for (int rsel = 0; rsel < 2; rsel++) {
            int r = bm0 + wm * 32 + mi * 16 + g + rsel * 8;
            if (r >= NN) continue;
            float xv = x[(size_t)r * INC];
            float x0c = t0[r] * xv;
            float x1c = t1[r] * xv;
#pragma unroll
            for (int ni = 0; ni < 8; ni++) {
                int col = bn0 + wn * 64 + ni * 8 + t * 2;
                float v0 = acc[mi][ni][rsel * 2 + 0] + x0c * __ldg(&p0[col]) +
                           x1c * __ldg(&p1[col]) + g_cb[col];
                float v1 = acc[mi][ni][rsel * 2 + 1] + x0c * __ldg(&p0[col + 1]) +
                           x1c * __ldg(&p1[col + 1]) + g_cb[col + 1];
                *(float2*)(out + (size_t)r * OUTC + col) = make_float2(v0, v1);
            }
        }
    }
}

// ------------------------- launch ------------------------------------------
extern "C" void kernel_launch(void* const* d_in, const int* in_sizes, int n_in,
                              void* d_out, int out_size) {
    const float* x  = (const float*)d_in[0];
    const int* e00  = (const int*)d_in[1];
    const int* e01  = (const int*)d_in[2];
    const int* e10  = (const int*)d_in[3];
    const int* e11  = (const int*)d_in[4];
    const float* t0 = (const float*)d_in[5];
    const float* t1 = (const float*)d_in[6];
    const float* W1 = (const float*)d_in[7];
    const float* b1 = (const float*)d_in[8];
    const float* W2 = (const float*)d_in[9];
    const float* b2 = (const float*)d_in[10];
    const float* W3 = (const float*)d_in[11];
    const float* b3 = (const float*)d_in[12];
    const float* W4 = (const float*)d_in[13];
    const float* b4 = (const float*)d_in[14];
    const float* p0 = (const float*)d_in[15];
    const float* p1 = (const float*)d_in[16];
    const float* p2 = (const float*)d_in[17];
    const float* p3 = (const float*)d_in[18];
    const float* p4 = (const float*)d_in[19];
    const float* p5 = (const float*)d_in[20];
    float* out = (float*)d_out;

    k_init<<<(4 * NN + 255) / 256, 256>>>();
    dim3 ge((EE + 255) / 256, 4);
    k_hist<<<ge, 256>>>(e00, e01, e10, e11);
    k_scan<<<4, 1024>>>();
    k_fill<<<ge, 256>>>(e00, e01, e10, e11);
    k_bmat<<<1024, 256>>>(W1, W2, W3, W4, p2, p3, p4, p5);
    k_cbias<<<1, 256>>>(b1, b2, b3, b4, p2, p3, p4, p5);
    k_agg<<<(4 * NN) / 8, 256>>>(x);
    dim3 gg(OUTC / BN, (NN + BM - 1) / BM);  // (2, 782)
    k_gemm<<<gg, 256>>>(x, t0, t1, p0, p1, out);
}

// round 3
// speedup vs baseline: 1.0012x; 1.0005x over previous
#include <cuda_runtime.h>
#include <cstdint>

#define NN   100000
#define INC  256
#define OUTC 256
#define EE   500000
#define KK   1024   // 4 * 256 concatenated aggregation channels

// ------------------------- device scratch (static: no allocs allowed) ------
__device__ float g_agg[(size_t)NN * KK];     // [N][4*256] aggregated features
__device__ float g_Bm[KK * OUTC];            // stacked W_k * diag(p_{k+2})
__device__ float g_cb[OUTC];                 // sum_k b_k * p_{k+2}
__device__ int   g_cnt[4][NN];
__device__ int   g_cur[4][NN];
__device__ int   g_rs[4][NN + 1];
__device__ float g_dis[4][NN];
__device__ int   g_srcv[4][EE];

// ------------------------- prep kernels ------------------------------------
__global__ void k_init() {
    int i = blockIdx.x * blockDim.x + threadIdx.x;
    if (i < 4 * NN) ((int*)g_cnt)[i] = 0;
}

__global__ void k_hist(const int* __restrict__ e0, const int* __restrict__ e1,
                       const int* __restrict__ e2, const int* __restrict__ e3) {
    int e = blockIdx.x * blockDim.x + threadIdx.x;
    if (e >= EE) return;
    int k = blockIdx.y;
    const int* ep = (k == 0) ? e0 : (k == 1) ? e1 : (k == 2) ? e2 : e3;
    int col = ep[EE + e];
    atomicAdd(&g_cnt[k][col], 1);
}

// one CTA per graph: exclusive scan of counts -> row_start, plus dis=rsqrt(deg)
__global__ void k_scan() {
    int k = blockIdx.x;
    int tid = threadIdx.x;
    const int CH = (NN + 1023) / 1024;
    int start = tid * CH;
    int end = min(start + CH, NN);
    int s = 0;
    for (int i = start; i < end; i++) s += g_cnt[k][i];
    __shared__ int sm[1024];
    sm[tid] = s;
    __syncthreads();
    for (int d = 1; d < 1024; d <<= 1) {
        int v = 0;
        if (tid >= d) v = sm[tid - d];
        __syncthreads();
        sm[tid] += v;
        __syncthreads();
    }
    int run = tid ? sm[tid - 1] : 0;
    for (int i = start; i < end; i++) {
        int c = g_cnt[k][i];
        g_rs[k][i] = run;
        run += c;
        g_dis[k][i] = rsqrtf((float)(c + 1));  // deg includes self-loop
        g_cur[k][i] = 0;
    }
    if (tid == 0) g_rs[k][NN] = sm[1023];
}

__global__ void k_fill(const int* __restrict__ e0, const int* __restrict__ e1,
                       const int* __restrict__ e2, const int* __restrict__ e3) {
    int e = blockIdx.x * blockDim.x + threadIdx.x;
    if (e >= EE) return;
    int k = blockIdx.y;
    const int* ep = (k == 0) ? e0 : (k == 1) ? e1 : (k == 2) ? e2 : e3;
    int row = ep[e];
    int col = ep[EE + e];
    int ofs = atomicAdd(&g_cur[k][col], 1);
    g_srcv[k][g_rs[k][col] + ofs] = row;
}

__global__ void k_bmat(const float* __restrict__ W1, const float* __restrict__ W2,
                       const float* __restrict__ W3, const float* __restrict__ W4,
                       const float* __restrict__ p2, const float* __restrict__ p3,
                       const float* __restrict__ p4, const float* __restrict__ p5) {
    int r = blockIdx.x;       // 0..1023 : k = r>>8, c = r&255
    int j = threadIdx.x;      // 0..255
    int k = r >> 8, c = r & 255;
    const float* W = (k == 0) ? W1 : (k == 1) ? W2 : (k == 2) ? W3 : W4;
    const float* p = (k == 0) ? p2 : (k == 1) ? p3 : (k == 2) ? p4 : p5;
    g_Bm[r * OUTC + j] = W[c * OUTC + j] * p[j];
}

__global__ void k_cbias(const float* __restrict__ b1, const float* __restrict__ b2,
                        const float* __restrict__ b3, const float* __restrict__ b4,
                        const float* __restrict__ p2, const float* __restrict__ p3,
                        const float* __restrict__ p4, const float* __restrict__ p5) {
    int j = threadIdx.x;
    g_cb[j] = b1[j] * p2[j] + b2[j] * p3[j] + b3[j] * p4[j] + b4[j] * p5[j];
}

// ------------------------- aggregation: AGG[n][k*256+c] = (Â_k x)[n][c] ----
// one warp per (node, graph) pair; lane owns 8 channels (2 float4)
__global__ void k_agg(const float* __restrict__ x) {
    int wid = threadIdx.x >> 5;
    int lane = threadIdx.x & 31;
    int pair = blockIdx.x * 8 + wid;       // 4e5 pairs
    int n = pair >> 2;
    int k = pair & 3;

    float dn = g_dis[k][n];
    int rs0 = g_rs[k][n];
    int rs1 = g_rs[k][n + 1];

    const float4* xr = (const float4*)(x + (size_t)n * INC);
    float sw = dn * dn;                    // self-loop norm = 1/deg
    float4 v0 = xr[lane * 2];
    float4 v1 = xr[lane * 2 + 1];
    float4 a0 = make_float4(sw * v0.x, sw * v0.y, sw * v0.z, sw * v0.w);
    float4 a1 = make_float4(sw * v1.x, sw * v1.y, sw * v1.z, sw * v1.w);

    for (int p = rs0; p < rs1; ++p) {
        int src = g_srcv[k][p];
        float w = g_dis[k][src] * dn;
        const float4* xs = (const float4*)(x + (size_t)src * INC);
        float4 u0 = xs[lane * 2];
        float4 u1 = xs[lane * 2 + 1];
        a0.x += w * u0.x; a0.y += w * u0.y; a0.z += w * u0.z; a0.w += w * u0.w;
        a1.x += w * u1.x; a1.y += w * u1.y; a1.z += w * u1.z; a1.w += w * u1.w;
    }

    float4* op = (float4*)(g_agg + (size_t)n * KK + k * OUTC);
    op[lane * 2] = a0;
    op[lane * 2 + 1] = a1;
}

// ------------------------- tf32 GEMM + fused epilogue -----------------------
// out[N,256] = AGG[N,1024] @ g_Bm[1024,256] + x0c*p0 + x1c*p1 + cb
__device__ __forceinline__ uint32_t f2tf(float f) {
    uint32_t r;
    asm("cvt.rna.tf32.f32 %0, %1;" : "=r"(r) : "f"(f));
    return r;
}

__device__ __forceinline__ void mma8(float* d, const uint32_t* a, const uint32_t* b) {
    asm volatile(
        "mma.sync.aligned.m16n8k8.row.col.f32.tf32.tf32.f32 "
        "{%0,%1,%2,%3}, {%4,%5,%6,%7}, {%8,%9}, {%0,%1,%2,%3};\n"
        : "+f"(d[0]), "+f"(d[1]), "+f"(d[2]), "+f"(d[3])
        : "r"(a[0]), "r"(a[1]), "r"(a[2]), "r"(a[3]), "r"(b[0]), "r"(b[1]));
}

#define BM 128
#define BN 128
#define BKC 16
#define NCHUNK (KK / BKC)   // 64

__global__ __launch_bounds__(256, 2) void k_gemm(
    const float* __restrict__ x,
    const float* __restrict__ t0, const float* __restrict__ t1,
    const float* __restrict__ p0, const float* __restrict__ p1,
    float* __restrict__ out) {
    __shared__ float As[2][BM][20];    // pad 16->20: conflict-free frag loads
    __shared__ float Bs[2][BKC][136];  // pad 128->136

    int tid = threadIdx.x;
    int lane = tid & 31;
    int wid = tid >> 5;
    int wm = wid >> 1;   // 0..3  (rows wm*32)
    int wn = wid & 1;    // 0..1  (cols wn*64)
    int bm0 = blockIdx.y * BM;
    int bn0 = blockIdx.x * BN;

    float acc[2][8][4];
#pragma unroll
    for (int mi = 0; mi < 2; mi++)
#pragma unroll
        for (int ni = 0; ni < 8; ni++)
#pragma unroll
            for (int q = 0; q < 4; q++) acc[mi][ni][q] = 0.f;

    float4 ra[2], rb[2];

    auto gld = [&](int c) {
        int k0 = c * BKC;
#pragma unroll
        for (int s = 0; s < 2; s++) {
            int row = (tid >> 2) + s * 64;
            int col = (tid & 3) * 4;
            int gr = bm0 + row;
            if (gr < NN)
                ra[s] = *(const float4*)(g_agg + (size_t)gr * KK + k0 + col);
            else
                ra[s] = make_float4(0.f, 0.f, 0.f, 0.f);
        }
#pragma unroll
        for (int s = 0; s < 2; s++) {
            int row = (tid >> 5) + s * 8;
            int col = (tid & 31) * 4;
            rb[s] = *(const float4*)(g_Bm + (size_t)(k0 + row) * OUTC + bn0 + col);
        }
    };

    auto sts = [&](int buf) {
#pragma unroll
        for (int s = 0; s < 2; s++) {
            int row = (tid >> 2) + s * 64;
            int col = (tid & 3) * 4;
            float* d = &As[buf][row][col];
            d[0] = __uint_as_float(f2tf(ra[s].x));
            d[1] = __uint_as_float(f2tf(ra[s].y));
            d[2] = __uint_as_float(f2tf(ra[s].z));
            d[3] = __uint_as_float(f2tf(ra[s].w));
        }
#pragma unroll
        for (int s = 0; s < 2; s++) {
            int row = (tid >> 5) + s * 8;
            int col = (tid & 31) * 4;
            float* d = &Bs[buf][row][col];
            d[0] = __uint_as_float(f2tf(rb[s].x));
            d[1] = __uint_as_float(f2tf(rb[s].y));
            d[2] = __uint_as_float(f2tf(rb[s].z));
            d[3] = __uint_as_float(f2tf(rb[s].w));
        }
    };

    int g = lane >> 2, t = lane & 3;

    auto compute = [&](int buf) {
#pragma unroll
        for (int ks = 0; ks < 2; ks++) {
            uint32_t af[2][4], bf[8][2];
#pragma unroll
            for (int mi = 0; mi < 2; mi++) {
                int r = wm * 32 + mi * 16 + g;
                int cc = ks * 8 + t;
                af[mi][0] = __float_as_uint(As[buf][r][cc]);
                af[mi][1] = __float_as_uint(As[buf][r + 8][cc]);
                af[mi][2] = __float_as_uint(As[buf][r][cc + 4]);
                af[mi][3] = __float_as_uint(As[buf][r + 8][cc + 4]);
            }
#pragma unroll
            for (int ni = 0; ni < 8; ni++) {
                int br = ks * 8 + t;
                int bc = wn * 64 + ni * 8 + g;
                bf[ni][0] = __float_as_uint(Bs[buf][br][bc]);
                bf[ni][1] = __float_as_uint(Bs[buf][br + 4][bc]);
            }
#pragma unroll
            for (int mi = 0; mi < 2; mi++)
#pragma unroll
                for (int ni = 0; ni < 8; ni++) mma8(acc[mi][ni], af[mi], bf[ni]);
        }
    };

    gld(0);
    sts(0);
    __syncthreads();
    int buf = 0;
    for (int c = 0; c < NCHUNK; c++) {
        if (c + 1 < NCHUNK) gld(c + 1);
        compute(buf);
        __syncthreads();
        if (c + 1 < NCHUNK) {
            sts(buf ^ 1);
            buf ^= 1;
            __syncthreads();
        }
    }

    // epilogue: + x0c*p0 + x1c*p1 + cb, store fp32
#pragma unroll
    for (int mi = 0; mi < 2; mi++) {
#pragma unroll
        for (int rsel = 0; rsel < 2; rsel++) {
            int r = bm0 + wm * 32 + mi * 16 + g + rsel * 8;
            if (r >= NN) continue;
            float xv = x[(size_t)r * INC];
            float x0c = t0[r] * xv;
            float x1c = t1[r] * xv;
#pragma unroll
            for (int ni = 0; ni < 8; ni++) {
                int col = bn0 + wn * 64 + ni * 8 + t * 2;
                float v0 = acc[mi][ni][rsel * 2 + 0] + x0c * __ldg(&p0[col]) +
                           x1c * __ldg(&p1[col]) + g_cb[col];
                float v1 = acc[mi][ni][rsel * 2 + 1] + x0c * __ldg(&p0[col + 1]) +
                           x1c * __ldg(&p1[col + 1]) + g_cb[col + 1];
                *(float2*)(out + (size_t)r * OUTC + col) = make_float2(v0, v1);
            }
        }
    }
}

// ------------------------- launch ------------------------------------------
extern "C" void kernel_launch(void* const* d_in, const int* in_sizes, int n_in,
                              void* d_out, int out_size) {
    const float* x  = (const float*)d_in[0];
    const int* e00  = (const int*)d_in[1];
    const int* e01  = (const int*)d_in[2];
    const int* e10  = (const int*)d_in[3];
    const int* e11  = (const int*)d_in[4];
    const float* t0 = (const float*)d_in[5];
    const float* t1 = (const float*)d_in[6];
    const float* W1 = (const float*)d_in[7];
    const float* b1 = (const float*)d_in[8];
    const float* W2 = (const float*)d_in[9];
    const float* b2 = (const float*)d_in[10];
    const float* W3 = (const float*)d_in[11];
    const float* b3 = (const float*)d_in[12];
    const float* W4 = (const float*)d_in[13];
    const float* b4 = (const float*)d_in[14];
    const float* p0 = (const float*)d_in[15];
    const float* p1 = (const float*)d_in[16];
    const float* p2 = (const float*)d_in[17];
    const float* p3 = (const float*)d_in[18];
    const float* p4 = (const float*)d_in[19];
    const float* p5 = (const float*)d_in[20];
    float* out = (float*)d_out;

    k_init<<<(4 * NN + 255) / 256, 256>>>();
    dim3 ge((EE + 255) / 256, 4);
    k_hist<<<ge, 256>>>(e00, e01, e10, e11);
    k_scan<<<4, 1024>>>();
    k_fill<<<ge, 256>>>(e00, e01, e10, e11);
    k_bmat<<<1024, 256>>>(W1, W2, W3, W4, p2, p3, p4, p5);
    k_cbias<<<1, 256>>>(b1, b2, b3, b4, p2, p3, p4, p5);
    k_agg<<<(4 * NN) / 8, 256>>>(x);
    dim3 gg(OUTC / BN, (NN + BM - 1) / BM);  // (2, 782)
    k_gemm<<<gg, 256>>>(x, t0, t1, p0, p1, out);
}

// round 4
// speedup vs baseline: 1.0013x; 1.0001x over previous
#include <cuda_runtime.h>
#include <cstdint>

#define NN   100000
#define INC  256
#define OUTC 256
#define EE   500000
#define KK   1024   // 4 * 256 concatenated aggregation channels

// ------------------------- device scratch (static: no allocs allowed) ------
__device__ float g_agg[(size_t)NN * KK];     // [N][4*256] aggregated features
__device__ float g_Bm[KK * OUTC];            // stacked W_k * diag(p_{k+2})
__device__ float g_cb[OUTC];                 // sum_k b_k * p_{k+2}
__device__ int   g_cnt[4][NN];
__device__ int   g_cur[4][NN];
__device__ int   g_rs[4][NN + 1];
__device__ float g_dis[4][NN];
__device__ int   g_srcv[4][EE];

// ------------------------- prep kernels ------------------------------------
__global__ void k_init() {
    int i = blockIdx.x * blockDim.x + threadIdx.x;
    if (i < 4 * NN) ((int*)g_cnt)[i] = 0;
}

__global__ void k_hist(const int* __restrict__ e0, const int* __restrict__ e1,
                       const int* __restrict__ e2, const int* __restrict__ e3) {
    int e = blockIdx.x * blockDim.x + threadIdx.x;
    if (e >= EE) return;
    int k = blockIdx.y;
    const int* ep = (k == 0) ? e0 : (k == 1) ? e1 : (k == 2) ? e2 : e3;
    int col = ep[EE + e];
    atomicAdd(&g_cnt[k][col], 1);
}

// one CTA per graph: exclusive scan of counts -> row_start, plus dis=rsqrt(deg)
__global__ void k_scan() {
    int k = blockIdx.x;
    int tid = threadIdx.x;
    const int CH = (NN + 1023) / 1024;
    int start = tid * CH;
    int end = min(start + CH, NN);
    int s = 0;
    for (int i = start; i < end; i++) s += g_cnt[k][i];
    __shared__ int sm[1024];
    sm[tid] = s;
    __syncthreads();
    for (int d = 1; d < 1024; d <<= 1) {
        int v = 0;
        if (tid >= d) v = sm[tid - d];
        __syncthreads();
        sm[tid] += v;
        __syncthreads();
    }
    int run = tid ? sm[tid - 1] : 0;
    for (int i = start; i < end; i++) {
        int c = g_cnt[k][i];
        g_rs[k][i] = run;
        run += c;
        g_dis[k][i] = rsqrtf((float)(c + 1));  // deg includes self-loop
        g_cur[k][i] = 0;
    }
    if (tid == 0) g_rs[k][NN] = sm[1023];
}

__global__ void k_fill(const int* __restrict__ e0, const int* __restrict__ e1,
                       const int* __restrict__ e2, const int* __restrict__ e3) {
    int e = blockIdx.x * blockDim.x + threadIdx.x;
    if (e >= EE) return;
    int k = blockIdx.y;
    const int* ep = (k == 0) ? e0 : (k == 1) ? e1 : (k == 2) ? e2 : e3;
    int row = ep[e];
    int col = ep[EE + e];
    int ofs = atomicAdd(&g_cur[k][col], 1);
    g_srcv[k][g_rs[k][col] + ofs] = row;
}

__global__ void k_bmat(const float* __restrict__ W1, const float* __restrict__ W2,
                       const float* __restrict__ W3, const float* __restrict__ W4,
                       const float* __restrict__ p2, const float* __restrict__ p3,
                       const float* __restrict__ p4, const float* __restrict__ p5) {
    int r = blockIdx.x;       // 0..1023 : k = r>>8, c = r&255
    int j = threadIdx.x;      // 0..255
    int k = r >> 8, c = r & 255;
    const float* W = (k == 0) ? W1 : (k == 1) ? W2 : (k == 2) ? W3 : W4;
    const float* p = (k == 0) ? p2 : (k == 1) ? p3 : (k == 2) ? p4 : p5;
    g_Bm[r * OUTC + j] = W[c * OUTC + j] * p[j];
}

__global__ void k_cbias(const float* __restrict__ b1, const float* __restrict__ b2,
                        const float* __restrict__ b3, const float* __restrict__ b4,
                        const float* __restrict__ p2, const float* __restrict__ p3,
                        const float* __restrict__ p4, const float* __restrict__ p5) {
    int j = threadIdx.x;
    g_cb[j] = b1[j] * p2[j] + b2[j] * p3[j] + b3[j] * p4[j] + b4[j] * p5[j];
}

// ------------------------- aggregation: AGG[n][k*256+c] = (Â_k x)[n][c] ----
// one warp per (node, graph) pair; lane owns 8 channels (2 float4)
__global__ void k_agg(const float* __restrict__ x) {
    int wid = threadIdx.x >> 5;
    int lane = threadIdx.x & 31;
    int pair = blockIdx.x * 8 + wid;       // 4e5 pairs
    int n = pair >> 2;
    int k = pair & 3;

    float dn = g_dis[k][n];
    int rs0 = g_rs[k][n];
    int rs1 = g_rs[k][n + 1];

    const float4* xr = (const float4*)(x + (size_t)n * INC);
    float sw = dn * dn;                    // self-loop norm = 1/deg
    float4 v0 = xr[lane * 2];
    float4 v1 = xr[lane * 2 + 1];
    float4 a0 = make_float4(sw * v0.x, sw * v0.y, sw * v0.z, sw * v0.w);
    float4 a1 = make_float4(sw * v1.x, sw * v1.y, sw * v1.z, sw * v1.w);

    for (int p = rs0; p < rs1; ++p) {
        int src = g_srcv[k][p];
        float w = g_dis[k][src] * dn;
        const float4* xs = (const float4*)(x + (size_t)src * INC);
        float4 u0 = xs[lane * 2];
        float4 u1 = xs[lane * 2 + 1];
        a0.x += w * u0.x; a0.y += w * u0.y; a0.z += w * u0.z; a0.w += w * u0.w;
        a1.x += w * u1.x; a1.y += w * u1.y; a1.z += w * u1.z; a1.w += w * u1.w;
    }

    float4* op = (float4*)(g_agg + (size_t)n * KK + k * OUTC);
    op[lane * 2] = a0;
    op[lane * 2 + 1] = a1;
}

// ------------------------- tf32 GEMM + fused epilogue -----------------------
// out[N,256] = AGG[N,1024] @ g_Bm[1024,256] + x0c*p0 + x1c*p1 + cb
__device__ __forceinline__ uint32_t f2tf(float f) {
    uint32_t r;
    asm("cvt.rna.tf32.f32 %0, %1;" : "=r"(r) : "f"(f));
    return r;
}

__device__ __forceinline__ void mma8(float* d, const uint32_t* a, const uint32_t* b) {
    asm volatile(
        "mma.sync.aligned.m16n8k8.row.col.f32.tf32.tf32.f32 "
        "{%0,%1,%2,%3}, {%4,%5,%6,%7}, {%8,%9}, {%0,%1,%2,%3};\n"
        : "+f"(d[0]), "+f"(d[1]), "+f"(d[2]), "+f"(d[3])
        : "r"(a[0]), "r"(a[1]), "r"(a[2]), "r"(a[3]), "r"(b[0]), "r"(b[1]));
}

#define BM 128
#define BN 128
#define BKC 16
#define NCHUNK (KK / BKC)   // 64

__global__ __launch_bounds__(256, 2) void k_gemm(
    const float* __restrict__ x,
    const float* __restrict__ t0, const float* __restrict__ t1,
    const float* __restrict__ p0, const float* __restrict__ p1,
    float* __restrict__ out) {
    __shared__ float As[2][BM][20];    // pad 16->20: conflict-free frag loads
    __shared__ float Bs[2][BKC][136];  // pad 128->136

    int tid = threadIdx.x;
    int lane = tid & 31;
    int wid = tid >> 5;
    int wm = wid >> 1;   // 0..3  (rows wm*32)
    int wn = wid & 1;    // 0..1  (cols wn*64)
    int bm0 = blockIdx.y * BM;
    int bn0 = blockIdx.x * BN;

    float acc[2][8][4];
#pragma unroll
    for (int mi = 0; mi < 2; mi++)
#pragma unroll
        for (int ni = 0; ni < 8; ni++)
#pragma unroll
            for (int q = 0; q < 4; q++) acc[mi][ni][q] = 0.f;

    float4 ra[2], rb[2];

    auto gld = [&](int c) {
        int k0 = c * BKC;
#pragma unroll
        for (int s = 0; s < 2; s++) {
            int row = (tid >> 2) + s * 64;
            int col = (tid & 3) * 4;
            int gr = bm0 + row;
            if (gr < NN)
                ra[s] = *(const float4*)(g_agg + (size_t)gr * KK + k0 + col);
            else
                ra[s] = make_float4(0.f, 0.f, 0.f, 0.f);
        }
#pragma unroll
        for (int s = 0; s < 2; s++) {
            int row = (tid >> 5) + s * 8;
            int col = (tid & 31) * 4;
            rb[s] = *(const float4*)(g_Bm + (size_t)(k0 + row) * OUTC + bn0 + col);
        }
    };

    auto sts = [&](int buf) {
#pragma unroll
        for (int s = 0; s < 2; s++) {
            int row = (tid >> 2) + s * 64;
            int col = (tid & 3) * 4;
            float* d = &As[buf][row][col];
            d[0] = __uint_as_float(f2tf(ra[s].x));
            d[1] = __uint_as_float(f2tf(ra[s].y));
            d[2] = __uint_as_float(f2tf(ra[s].z));
            d[3] = __uint_as_float(f2tf(ra[s].w));
        }
#pragma unroll
        for (int s = 0; s < 2; s++) {
            int row = (tid >> 5) + s * 8;
            int col = (tid & 31) * 4;
            float* d = &Bs[buf][row][col];
            d[0] = __uint_as_float(f2tf(rb[s].x));
            d[1] = __uint_as_float(f2tf(rb[s].y));
            d[2] = __uint_as_float(f2tf(rb[s].z));
            d[3] = __uint_as_float(f2tf(rb[s].w));
        }
    };

    int g = lane >> 2, t = lane & 3;

    auto compute = [&](int buf) {
#pragma unroll
        for (int ks = 0; ks < 2; ks++) {
            uint32_t af[2][4], bf[8][2];
#pragma unroll
            for (int mi = 0; mi < 2; mi++) {
                int r = wm * 32 + mi * 16 + g;
                int cc = ks * 8 + t;
                af[mi][0] = __float_as_uint(As[buf][r][cc]);
                af[mi][1] = __float_as_uint(As[buf][r + 8][cc]);
                af[mi][2] = __float_as_uint(As[buf][r][cc + 4]);
                af[mi][3] = __float_as_uint(As[buf][r + 8][cc + 4]);
            }
#pragma unroll
            for (int ni = 0; ni < 8; ni++) {
                int br = ks * 8 + t;
                int bc = wn * 64 + ni * 8 + g;
                bf[ni][0] = __float_as_uint(Bs[buf][br][bc]);
                bf[ni][1] = __float_as_uint(Bs[buf][br + 4][bc]);
            }
#pragma unroll
            for (int mi = 0; mi < 2; mi++)
#pragma unroll
                for (int ni = 0; ni < 8; ni++) mma8(acc[mi][ni], af[mi], bf[ni]);
        }
    };

    gld(0);
    sts(0);
    __syncthreads();
    int buf = 0;
    for (int c = 0; c < NCHUNK; c++) {
        if (c + 1 < NCHUNK) gld(c + 1);
        compute(buf);
        __syncthreads();
        if (c + 1 < NCHUNK) {
            sts(buf ^ 1);
            buf ^= 1;
            __syncthreads();
        }
    }

    // epilogue: + x0c*p0 + x1c*p1 + cb, store fp32
#pragma unroll
    for (int mi = 0; mi < 2; mi++) {
#pragma unroll
        for (int rsel = 0; rsel < 2; rsel++) {
            int r = bm0 + wm * 32 + mi * 16 + g + rsel * 8;
            if (r >= NN) continue;
            float xv = x[(size_t)r * INC];
            float x0c = t0[r] * xv;
            float x1c = t1[r] * xv;
#pragma unroll
            for (int ni = 0; ni < 8; ni++) {
                int col = bn0 + wn * 64 + ni * 8 + t * 2;
                float v0 = acc[mi][ni][rsel * 2 + 0] + x0c * __ldg(&p0[col]) +
                           x1c * __ldg(&p1[col]) + g_cb[col];
                float v1 = acc[mi][ni][rsel * 2 + 1] + x0c * __ldg(&p0[col + 1]) +
                           x1c * __ldg(&p1[col + 1]) + g_cb[col + 1];
                *(float2*)(out + (size_t)r * OUTC + col) = make_float2(v0, v1);
            }
        }
    }
}

// ------------------------- launch ------------------------------------------
extern "C" void kernel_launch(void* const* d_in, const int* in_sizes, int n_in,
                              void* d_out, int out_size) {
    const float* x  = (const float*)d_in[0];
    const int* e00  = (const int*)d_in[1];
    const int* e01  = (const int*)d_in[2];
    const int* e10  = (const int*)d_in[3];
    const int* e11  = (const int*)d_in[4];
    const float* t0 = (const float*)d_in[5];
    const float* t1 = (const float*)d_in[6];
    const float* W1 = (const float*)d_in[7];
    const float* b1 = (const float*)d_in[8];
    const float* W2 = (const float*)d_in[9];
    const float* b2 = (const float*)d_in[10];
    const float* W3 = (const float*)d_in[11];
    const float* b3 = (const float*)d_in[12];
    const float* W4 = (const float*)d_in[13];
    const float* b4 = (const float*)d_in[14];
    const float* p0 = (const float*)d_in[15];
    const float* p1 = (const float*)d_in[16];
    const float* p2 = (const float*)d_in[17];
    const float* p3 = (const float*)d_in[18];
    const float* p4 = (const float*)d_in[19];
    const float* p5 = (const float*)d_in[20];
    float* out = (float*)d_out;

    k_init<<<(4 * NN + 255) / 256, 256>>>();
    dim3 ge((EE + 255) / 256, 4);
    k_hist<<<ge, 256>>>(e00, e01, e10, e11);
    k_scan<<<4, 1024>>>();
    k_fill<<<ge, 256>>>(e00, e01, e10, e11);
    k_bmat<<<1024, 256>>>(W1, W2, W3, W4, p2, p3, p4, p5);
    k_cbias<<<1, 256>>>(b1, b2, b3, b4, p2, p3, p4, p5);
    k_agg<<<(4 * NN) / 8, 256>>>(x);
    dim3 gg(OUTC / BN, (NN + BM - 1) / BM);  // (2, 782)
    k_gemm<<<gg, 256>>>(x, t0, t1, p0, p1, out);
}

// round 5
// speedup vs baseline: 1.0017x; 1.0004x over previous
#include <cuda_runtime.h>
#include <cstdint>

#define NN   100000
#define INC  256
#define OUTC 256
#define EE   500000
#define KK   1024   // 4 * 256 concatenated aggregation channels

// ------------------------- device scratch (static: no allocs allowed) ------
__device__ float g_agg[(size_t)NN * KK];     // [N][4*256] aggregated features
__device__ float g_Bm[KK * OUTC];            // stacked W_k * diag(p_{k+2})
__device__ float g_cb[OUTC];                 // sum_k b_k * p_{k+2}
__device__ int   g_cnt[4][NN];
__device__ int   g_cur[4][NN];
__device__ int   g_rs[4][NN + 1];
__device__ float g_dis[4][NN];
__device__ int   g_srcv[4][EE];

// ------------------------- prep kernels ------------------------------------
__global__ void k_init() {
    int i = blockIdx.x * blockDim.x + threadIdx.x;
    if (i < 4 * NN) ((int*)g_cnt)[i] = 0;
}

__global__ void k_hist(const int* __restrict__ e0, const int* __restrict__ e1,
                       const int* __restrict__ e2, const int* __restrict__ e3) {
    int e = blockIdx.x * blockDim.x + threadIdx.x;
    if (e >= EE) return;
    int k = blockIdx.y;
    const int* ep = (k == 0) ? e0 : (k == 1) ? e1 : (k == 2) ? e2 : e3;
    int col = ep[EE + e];
    atomicAdd(&g_cnt[k][col], 1);
}

// one CTA per graph: exclusive scan of counts -> row_start, plus dis=rsqrt(deg)
__global__ void k_scan() {
    int k = blockIdx.x;
    int tid = threadIdx.x;
    const int CH = (NN + 1023) / 1024;
    int start = tid * CH;
    int end = min(start + CH, NN);
    int s = 0;
    for (int i = start; i < end; i++) s += g_cnt[k][i];
    __shared__ int sm[1024];
    sm[tid] = s;
    __syncthreads();
    for (int d = 1; d < 1024; d <<= 1) {
        int v = 0;
        if (tid >= d) v = sm[tid - d];
        __syncthreads();
        sm[tid] += v;
        __syncthreads();
    }
    int run = tid ? sm[tid - 1] : 0;
    for (int i = start; i < end; i++) {
        int c = g_cnt[k][i];
        g_rs[k][i] = run;
        run += c;
        g_dis[k][i] = rsqrtf((float)(c + 1));  // deg includes self-loop
        g_cur[k][i] = 0;
    }
    if (tid == 0) g_rs[k][NN] = sm[1023];
}

__global__ void k_fill(const int* __restrict__ e0, const int* __restrict__ e1,
                       const int* __restrict__ e2, const int* __restrict__ e3) {
    int e = blockIdx.x * blockDim.x + threadIdx.x;
    if (e >= EE) return;
    int k = blockIdx.y;
    const int* ep = (k == 0) ? e0 : (k == 1) ? e1 : (k == 2) ? e2 : e3;
    int row = ep[e];
    int col = ep[EE + e];
    int ofs = atomicAdd(&g_cur[k][col], 1);
    g_srcv[k][g_rs[k][col] + ofs] = row;
}

__global__ void k_bmat(const float* __restrict__ W1, const float* __restrict__ W2,
                       const float* __restrict__ W3, const float* __restrict__ W4,
                       const float* __restrict__ p2, const float* __restrict__ p3,
                       const float* __restrict__ p4, const float* __restrict__ p5) {
    int r = blockIdx.x;       // 0..1023 : k = r>>8, c = r&255
    int j = threadIdx.x;      // 0..255
    int k = r >> 8, c = r & 255;
    const float* W = (k == 0) ? W1 : (k == 1) ? W2 : (k == 2) ? W3 : W4;
    const float* p = (k == 0) ? p2 : (k == 1) ? p3 : (k == 2) ? p4 : p5;
    g_Bm[r * OUTC + j] = W[c * OUTC + j] * p[j];
}

__global__ void k_cbias(const float* __restrict__ b1, const float* __restrict__ b2,
                        const float* __restrict__ b3, const float* __restrict__ b4,
                        const float* __restrict__ p2, const float* __restrict__ p3,
                        const float* __restrict__ p4, const float* __restrict__ p5) {
    int j = threadIdx.x;
    g_cb[j] = b1[j] * p2[j] + b2[j] * p3[j] + b3[j] * p4[j] + b4[j] * p5[j];
}

// ------------------------- aggregation: AGG[n][k*256+c] = (Â_k x)[n][c] ----
// one warp per (node, graph) pair; lane owns 8 channels (2 float4)
__global__ void k_agg(const float* __restrict__ x) {
    int wid = threadIdx.x >> 5;
    int lane = threadIdx.x & 31;
    int pair = blockIdx.x * 8 + wid;       // 4e5 pairs
    int n = pair >> 2;
    int k = pair & 3;

    float dn = g_dis[k][n];
    int rs0 = g_rs[k][n];
    int rs1 = g_rs[k][n + 1];

    const float4* xr = (const float4*)(x + (size_t)n * INC);
    float sw = dn * dn;                    // self-loop norm = 1/deg
    float4 v0 = xr[lane * 2];
    float4 v1 = xr[lane * 2 + 1];
    float4 a0 = make_float4(sw * v0.x, sw * v0.y, sw * v0.z, sw * v0.w);
    float4 a1 = make_float4(sw * v1.x, sw * v1.y, sw * v1.z, sw * v1.w);

    for (int p = rs0; p < rs1; ++p) {
        int src = g_srcv[k][p];
        float w = g_dis[k][src] * dn;
        const float4* xs = (const float4*)(x + (size_t)src * INC);
        float4 u0 = xs[lane * 2];
        float4 u1 = xs[lane * 2 + 1];
        a0.x += w * u0.x; a0.y += w * u0.y; a0.z += w * u0.z; a0.w += w * u0.w;
        a1.x += w * u1.x; a1.y += w * u1.y; a1.z += w * u1.z; a1.w += w * u1.w;
    }

    float4* op = (float4*)(g_agg + (size_t)n * KK + k * OUTC);
    op[lane * 2] = a0;
    op[lane * 2 + 1] = a1;
}

// ------------------------- tf32 GEMM + fused epilogue -----------------------
// out[N,256] = AGG[N,1024] @ g_Bm[1024,256] + x0c*p0 + x1c*p1 + cb
__device__ __forceinline__ uint32_t f2tf(float f) {
    uint32_t r;
    asm("cvt.rna.tf32.f32 %0, %1;" : "=r"(r) : "f"(f));
    return r;
}

__device__ __forceinline__ void mma8(float* d, const uint32_t* a, const uint32_t* b) {
    asm volatile(
        "mma.sync.aligned.m16n8k8.row.col.f32.tf32.tf32.f32 "
        "{%0,%1,%2,%3}, {%4,%5,%6,%7}, {%8,%9}, {%0,%1,%2,%3};\n"
        : "+f"(d[0]), "+f"(d[1]), "+f"(d[2]), "+f"(d[3])
        : "r"(a[0]), "r"(a[1]), "r"(a[2]), "r"(a[3]), "r"(b[0]), "r"(b[1]));
}

#define BM 128
#define BN 128
#define BKC 16
#define NCHUNK (KK / BKC)   // 64

__global__ __launch_bounds__(256, 2) void k_gemm(
    const float* __restrict__ x,
    const float* __restrict__ t0, const float* __restrict__ t1,
    const float* __restrict__ p0, const float* __restrict__ p1,
    float* __restrict__ out) {
    __shared__ float As[2][BM][20];    // pad 16->20: conflict-free frag loads
    __shared__ float Bs[2][BKC][136];  // pad 128->136

    int tid = threadIdx.x;
    int lane = tid & 31;
    int wid = tid >> 5;
    int wm = wid >> 1;   // 0..3  (rows wm*32)
    int wn = wid & 1;    // 0..1  (cols wn*64)
    int bm0 = blockIdx.y * BM;
    int bn0 = blockIdx.x * BN;

    float acc[2][8][4];
#pragma unroll
    for (int mi = 0; mi < 2; mi++)
#pragma unroll
        for (int ni = 0; ni < 8; ni++)
#pragma unroll
            for (int q = 0; q < 4; q++) acc[mi][ni][q] = 0.f;

    float4 ra[2], rb[2];

    auto gld = [&](int c) {
        int k0 = c * BKC;
#pragma unroll
        for (int s = 0; s < 2; s++) {
            int row = (tid >> 2) + s * 64;
            int col = (tid & 3) * 4;
            int gr = bm0 + row;
            if (gr < NN)
                ra[s] = *(const float4*)(g_agg + (size_t)gr * KK + k0 + col);
            else
                ra[s] = make_float4(0.f, 0.f, 0.f, 0.f);
        }
#pragma unroll
        for (int s = 0; s < 2; s++) {
            int row = (tid >> 5) + s * 8;
            int col = (tid & 31) * 4;
            rb[s] = *(const float4*)(g_Bm + (size_t)(k0 + row) * OUTC + bn0 + col);
        }
    };

    auto sts = [&](int buf) {
#pragma unroll
        for (int s = 0; s < 2; s++) {
            int row = (tid >> 2) + s * 64;
            int col = (tid & 3) * 4;
            float* d = &As[buf][row][col];
            d[0] = __uint_as_float(f2tf(ra[s].x));
            d[1] = __uint_as_float(f2tf(ra[s].y));
            d[2] = __uint_as_float(f2tf(ra[s].z));
            d[3] = __uint_as_float(f2tf(ra[s].w));
        }
#pragma unroll
        for (int s = 0; s < 2; s++) {
            int row = (tid >> 5) + s * 8;
            int col = (tid & 31) * 4;
            float* d = &Bs[buf][row][col];
            d[0] = __uint_as_float(f2tf(rb[s].x));
            d[1] = __uint_as_float(f2tf(rb[s].y));
            d[2] = __uint_as_float(f2tf(rb[s].z));
            d[3] = __uint_as_float(f2tf(rb[s].w));
        }
    };

    int g = lane >> 2, t = lane & 3;

    auto compute = [&](int buf) {
#pragma unroll
        for (int ks = 0; ks < 2; ks++) {
            uint32_t af[2][4], bf[8][2];
#pragma unroll
            for (int mi = 0; mi < 2; mi++) {
                int r = wm * 32 + mi * 16 + g;
                int cc = ks * 8 + t;
                af[mi][0] = __float_as_uint(As[buf][r][cc]);
                af[mi][1] = __float_as_uint(As[buf][r + 8][cc]);
                af[mi][2] = __float_as_uint(As[buf][r][cc + 4]);
                af[mi][3] = __float_as_uint(As[buf][r + 8][cc + 4]);
            }
#pragma unroll
            for (int ni = 0; ni < 8; ni++) {
                int br = ks * 8 + t;
                int bc = wn * 64 + ni * 8 + g;
                bf[ni][0] = __float_as_uint(Bs[buf][br][bc]);
                bf[ni][1] = __float_as_uint(Bs[buf][br + 4][bc]);
            }
#pragma unroll
            for (int mi = 0; mi < 2; mi++)
#pragma unroll
                for (int ni = 0; ni < 8; ni++) mma8(acc[mi][ni], af[mi], bf[ni]);
        }
    };

    gld(0);
    sts(0);
    __syncthreads();
    int buf = 0;
    for (int c = 0; c < NCHUNK; c++) {
        if (c + 1 < NCHUNK) gld(c + 1);
        compute(buf);
        __syncthreads();
        if (c + 1 < NCHUNK) {
            sts(buf ^ 1);
            buf ^= 1;
            __syncthreads();
        }
    }

    // epilogue: + x0c*p0 + x1c*p1 + cb, store fp32
#pragma unroll
    for (int mi = 0; mi < 2; mi++) {
#pragma unroll
        for (int rsel = 0; rsel < 2; rsel++) {
            int r = bm0 + wm * 32 + mi * 16 + g + rsel * 8;
            if (r >= NN) continue;
            float xv = x[(size_t)r * INC];
            float x0c = t0[r] * xv;
            float x1c = t1[r] * xv;
#pragma unroll
            for (int ni = 0; ni < 8; ni++) {
                int col = bn0 + wn * 64 + ni * 8 + t * 2;
                float v0 = acc[mi][ni][rsel * 2 + 0] + x0c * __ldg(&p0[col]) +
                           x1c * __ldg(&p1[col]) + g_cb[col];
                float v1 = acc[mi][ni][rsel * 2 + 1] + x0c * __ldg(&p0[col + 1]) +
                           x1c * __ldg(&p1[col + 1]) + g_cb[col + 1];
                *(float2*)(out + (size_t)r * OUTC + col) = make_float2(v0, v1);
            }
        }
    }
}

// ------------------------- launch ------------------------------------------
extern "C" void kernel_launch(void* const* d_in, const int* in_sizes, int n_in,
                              void* d_out, int out_size) {
    const float* x  = (const float*)d_in[0];
    const int* e00  = (const int*)d_in[1];
    const int* e01  = (const int*)d_in[2];
    const int* e10  = (const int*)d_in[3];
    const int* e11  = (const int*)d_in[4];
    const float* t0 = (const float*)d_in[5];
    const float* t1 = (const float*)d_in[6];
    const float* W1 = (const float*)d_in[7];
    const float* b1 = (const float*)d_in[8];
    const float* W2 = (const float*)d_in[9];
    const float* b2 = (const float*)d_in[10];
    const float* W3 = (const float*)d_in[11];
    const float* b3 = (const float*)d_in[12];
    const float* W4 = (const float*)d_in[13];
    const float* b4 = (const float*)d_in[14];
    const float* p0 = (const float*)d_in[15];
    const float* p1 = (const float*)d_in[16];
    const float* p2 = (const float*)d_in[17];
    const float* p3 = (const float*)d_in[18];
    const float* p4 = (const float*)d_in[19];
    const float* p5 = (const float*)d_in[20];
    float* out = (float*)d_out;

    k_init<<<(4 * NN + 255) / 256, 256>>>();
    dim3 ge((EE + 255) / 256, 4);
    k_hist<<<ge, 256>>>(e00, e01, e10, e11);
    k_scan<<<4, 1024>>>();
    k_fill<<<ge, 256>>>(e00, e01, e10, e11);
    k_bmat<<<1024, 256>>>(W1, W2, W3, W4, p2, p3, p4, p5);
    k_cbias<<<1, 256>>>(b1, b2, b3, b4, p2, p3, p4, p5);
    k_agg<<<(4 * NN) / 8, 256>>>(x);
    dim3 gg(OUTC / BN, (NN + BM - 1) / BM);  // (2, 782)
    k_gemm<<<gg, 256>>>(x, t0, t1, p0, p1, out);
}